// round 10
// baseline (speedup 1.0000x reference)
#include <cuda_runtime.h>
#include <math.h>

// Problem constants
#define BB 64
#define JJ 42
#define PP 16384
#define JG 6            // joint groups
#define JT 7            // joints per group (JG*JT == JJ)
#define PC 4            // P chunks
#define PPB (PP/PC)     // 4096 points per block
#define THREADS 256
#define NF4 (PPB*3/4)   // 3072 float4 per block tile (48KB)
#define NWARP (THREADS/32)
#define GRID (BB*JG*PC)     // 1536 blocks
#define NBJ (BB*JJ)         // 2688
#define CHUNK 1024          // points per SoA chunk (4 chunks)

// Scratch: per-(b,j) partial min-squared-distance, one slot per P-chunk.
__device__ float g_partial[NBJ * PC];
__device__ unsigned int g_count;   // zero at module load; last block resets to 0

typedef unsigned long long u64;

__device__ __forceinline__ u64 pack2(float lo, float hi) {
    u64 r; asm("mov.b64 %0, {%1, %2};" : "=l"(r) : "f"(lo), "f"(hi)); return r;
}
__device__ __forceinline__ u64 fma2(u64 a, u64 b, u64 c) {
    u64 d; asm("fma.rn.f32x2 %0, %1, %2, %3;" : "=l"(d) : "l"(a), "l"(b), "l"(c)); return d;
}
__device__ __forceinline__ u64 mul2(u64 a, u64 b) {
    u64 d; asm("mul.rn.f32x2 %0, %1, %2;" : "=l"(d) : "l"(a), "l"(b)); return d;
}
// fma2 with result split into halves (mov.b64 split = register renaming, free).
__device__ __forceinline__ void fma2_split(u64 a, u64 b, u64 c, float& lo, float& hi) {
    asm("{ .reg .b64 t; fma.rn.f32x2 t, %2, %3, %4; mov.b64 {%0, %1}, t; }"
        : "=f"(lo), "=f"(hi) : "l"(a), "l"(b), "l"(c));
}

__global__ __launch_bounds__(THREADS, 2) void sdl_fused_kernel(
    const float* __restrict__ pred,   // [B,J,3]
    const float* __restrict__ pts,    // [B,P,3]
    const float* __restrict__ gt,     // [B,J]
    float* __restrict__ out)
{
    // 48KB buffer: staged linear, then transposed in-place (chunked) to SoA:
    // chunk ch floats [3072*ch .. +3072): px[1024] | py[1024] | pz[1024].
    __shared__ float4 s_buf4[NF4];
    float* s_f = (float*)s_buf4;

    const int blk = blockIdx.x;
    const int pc = blk % PC;
    const int jg = (blk / PC) % JG;
    const int b  = blk / (PC * JG);
    const int t  = threadIdx.x;

    // ---- Stage phase 1: coalesced LDG.128 -> linear smem ----
    const float4* src = (const float4*)(pts + ((size_t)b * PP + (size_t)pc * PPB) * 3);
#pragma unroll
    for (int k = 0; k < NF4 / THREADS; k++)
        s_buf4[k * THREADS + t] = src[k * THREADS + t];

    // Joint constants: packed f32x2 (duplicated lanes), built once.
    u64 cx[JT], cy[JT], cz[JT];
    float accL[JT], accH[JT];
    const float* jp = pred + (size_t)(b * JJ + jg * JT) * 3;
#pragma unroll
    for (int j = 0; j < JT; j++) {
        float mxv = -2.0f * jp[j * 3 + 0];
        float myv = -2.0f * jp[j * 3 + 1];
        float mzv = -2.0f * jp[j * 3 + 2];
        cx[j] = pack2(mxv, mxv);
        cy[j] = pack2(myv, myv);
        cz[j] = pack2(mzv, mzv);
        accL[j] = 3.0e38f; accH[j] = 3.0e38f;
    }
    __syncthreads();

    // ---- Stage phase 2: in-place AoS->SoA per chunk (compile-time indexing) ----
#pragma unroll
    for (int ch = 0; ch < 4; ch++) {
        const int F = 3072 * ch;
        // Thread t owns local points 4t..4t+3 of this chunk = floats F+12t..F+12t+11.
        float4 A  = s_buf4[(F / 4) + 3 * t + 0];
        float4 Bv = s_buf4[(F / 4) + 3 * t + 1];
        float4 C  = s_buf4[(F / 4) + 3 * t + 2];
        __syncthreads();   // everyone has read before anyone overwrites
        ((float4*)(s_f + F +        0))[t] = make_float4(A.x,  A.w,  Bv.z, C.y);  // px
        ((float4*)(s_f + F + CHUNK    ))[t] = make_float4(A.y,  Bv.x, Bv.w, C.z);  // py
        ((float4*)(s_f + F + 2*CHUNK  ))[t] = make_float4(A.z,  Bv.y, C.x,  C.w);  // pz
        __syncthreads();
    }

    // ---- Main loop: packed f32x2, operands straight from LDS.64 ----
    const u64* sp = (const u64*)s_f;
#pragma unroll
    for (int ch = 0; ch < 4; ch++) {
        const int F2 = (3072 * ch) / 2;           // u64 index of chunk base
        // Pair A: points (2t, 2t+1); Pair B: points (512+2t, 512+2t+1).
        u64 xA = sp[F2 + t];
        u64 yA = sp[F2 + CHUNK/2 + t];
        u64 zA = sp[F2 + CHUNK   + t];
        u64 xB = sp[F2 + 256 + t];
        u64 yB = sp[F2 + CHUNK/2 + 256 + t];
        u64 zB = sp[F2 + CHUNK   + 256 + t];

        u64 b2A = fma2(zA, zA, fma2(yA, yA, mul2(xA, xA)));
        u64 b2B = fma2(zB, zB, fma2(yB, yB, mul2(xB, xB)));

#pragma unroll
        for (int j = 0; j < JT; j++) {
            float la, ha, lb, hb;
            fma2_split(cx[j], xA, fma2(cy[j], yA, fma2(cz[j], zA, b2A)), la, ha);
            fma2_split(cx[j], xB, fma2(cy[j], yB, fma2(cz[j], zB, b2B)), lb, hb);
            accL[j] = fminf(accL[j], fminf(la, lb));
            accH[j] = fminf(accH[j], fminf(ha, hb));
        }
    }

    // Epilogue: merge halves, fold |a|^2 (recomputed; shift commutes with min).
    float acc[JT];
#pragma unroll
    for (int j = 0; j < JT; j++) {
        float ax = jp[j * 3 + 0];
        float ay = jp[j * 3 + 1];
        float az = jp[j * 3 + 2];
        acc[j] = fminf(accL[j], accH[j]) + fmaf(az, az, fmaf(ay, ay, ax * ax));
    }

    // Warp min-reduce.
#pragma unroll
    for (int j = 0; j < JT; j++) {
        float v = acc[j];
        v = fminf(v, __shfl_xor_sync(0xFFFFFFFFu, v, 16));
        v = fminf(v, __shfl_xor_sync(0xFFFFFFFFu, v, 8));
        v = fminf(v, __shfl_xor_sync(0xFFFFFFFFu, v, 4));
        v = fminf(v, __shfl_xor_sync(0xFFFFFFFFu, v, 2));
        v = fminf(v, __shfl_xor_sync(0xFFFFFFFFu, v, 1));
        acc[j] = v;
    }

    // Reuse smem as reduction scratch (all main-loop LDS done).
    __syncthreads();
    float* sred = s_f;                      // [0..55]: smin[8][7]
    unsigned* sflag = ((unsigned*)s_f) + 64;
    float* ssum = s_f + 72;                 // per-warp sums

    const int w = t >> 5, l = t & 31;
    if (l == 0) {
#pragma unroll
        for (int j = 0; j < JT; j++) sred[w * JT + j] = acc[j];
    }
    __syncthreads();

    if (t < JT) {
        float v = sred[t];
#pragma unroll
        for (int wi = 1; wi < NWARP; wi++) v = fminf(v, sred[wi * JT + t]);
        g_partial[(size_t)(b * JJ + jg * JT + t) * PC + pc] = v;
    }

    // ---- last-block finalize (fused MSE) ----
    __threadfence();
    __syncthreads();
    if (t == 0) {
        unsigned c = atomicAdd(&g_count, 1u);
        *sflag = (c == (unsigned)(GRID - 1)) ? 1u : 0u;
    }
    __syncthreads();
    if (*sflag == 0u) return;

    float s = 0.0f;
    const float4* gp = (const float4*)g_partial;
#pragma unroll 1
    for (int i = t; i < NBJ; i += THREADS) {
        float4 v = __ldcg(gp + i);
        float m = fminf(fminf(v.x, v.y), fminf(v.z, v.w));
        m = fmaxf(m, 0.0f);
        float d = sqrtf(m) - gt[i];
        s = fmaf(d, d, s);
    }
    s += __shfl_xor_sync(0xFFFFFFFFu, s, 16);
    s += __shfl_xor_sync(0xFFFFFFFFu, s, 8);
    s += __shfl_xor_sync(0xFFFFFFFFu, s, 4);
    s += __shfl_xor_sync(0xFFFFFFFFu, s, 2);
    s += __shfl_xor_sync(0xFFFFFFFFu, s, 1);
    __syncthreads();
    if (l == 0) ssum[w] = s;
    __syncthreads();
    if (t == 0) {
        float tot = ssum[0];
#pragma unroll
        for (int wi = 1; wi < NWARP; wi++) tot += ssum[wi];
        out[0] = tot / (float)NBJ;
        g_count = 0;   // reset for next graph replay
    }
}

extern "C" void kernel_launch(void* const* d_in, const int* in_sizes, int n_in,
                              void* d_out, int out_size) {
    (void)in_sizes; (void)n_in; (void)out_size;
    const float* pred = (const float*)d_in[0];   // [64,42,3]
    const float* pts  = (const float*)d_in[1];   // [64,16384,3]
    const float* gt   = (const float*)d_in[2];   // [64,42]
    float* out = (float*)d_out;

    sdl_fused_kernel<<<GRID, THREADS>>>(pred, pts, gt, out);
}

// round 11
// speedup vs baseline: 1.3269x; 1.3269x over previous
#include <cuda_runtime.h>
#include <math.h>

// Problem constants
#define BB 64
#define JJ 42
#define PP 16384
#define JG 3            // joint groups
#define JT 14           // joints per group (JG*JT == JJ)
#define PC 4            // P chunks
#define PPB (PP/PC)     // 4096 points per block
#define THREADS 256
#define NF4 (PPB*3/4)   // 3072 float4 per block tile (48KB)
#define NWARP (THREADS/32)
#define GRID (BB*JG*PC)     // 768 blocks
#define NBJ (BB*JJ)         // 2688

// Scratch: per-(b,j) partial min-squared-distance, one slot per P-chunk.
__device__ float g_partial[NBJ * PC];
__device__ unsigned int g_count;   // zero at module load; last block resets to 0

__global__ __launch_bounds__(THREADS, 2) void sdl_fused_kernel(
    const float* __restrict__ pred,   // [B,J,3]
    const float* __restrict__ pts,    // [B,P,3]
    const float* __restrict__ gt,     // [B,J]
    float* __restrict__ out)
{
    // 48KB AoS point tile; reduction scratch aliases it after the main loop.
    __shared__ float4 s_buf4[NF4];

    const int blk = blockIdx.x;
    const int pc = blk % PC;
    const int jg = (blk / PC) % JG;
    const int b  = blk / (PC * JG);
    const int t  = threadIdx.x;

    // ---- Stage: coalesced LDG.128, only 3 loads in flight (low live regs) ----
    const float4* src = (const float4*)(pts + ((size_t)b * PP + (size_t)pc * PPB) * 3);
#pragma unroll 3
    for (int k = 0; k < NF4 / THREADS; k++)
        s_buf4[k * THREADS + t] = src[k * THREADS + t];

    // Joint constants AFTER staging stores: constant regs never coexist with
    // the staging load burst. (a2 recomputed in epilogue, not kept live.)
    float mx[JT], my[JT], mz[JT], acc[JT];
    const float* jp = pred + (size_t)(b * JJ + jg * JT) * 3;
#pragma unroll
    for (int j = 0; j < JT; j++) {
        mx[j] = -2.0f * jp[j * 3 + 0];
        my[j] = -2.0f * jp[j * 3 + 1];
        mz[j] = -2.0f * jp[j * 3 + 2];
        acc[j] = 3.0e38f;
    }
    __syncthreads();

    // ---- Main loop: 4 points/iter from SMEM; per-q scalars keep live set ~84 ----
#pragma unroll 1
    for (int it = 0; it < PPB / (4 * THREADS); it++) {
        const int base = (it * THREADS + t) * 3;
        float4 A  = s_buf4[base + 0];
        float4 Bv = s_buf4[base + 1];
        float4 C  = s_buf4[base + 2];

#pragma unroll
        for (int q = 0; q < 4; q++) {
            float px, py, pz;
            if (q == 0)      { px = A.x;  py = A.y;  pz = A.z;  }
            else if (q == 1) { px = A.w;  py = Bv.x; pz = Bv.y; }
            else if (q == 2) { px = Bv.z; py = Bv.w; pz = C.x;  }
            else             { px = C.y;  py = C.z;  pz = C.w;  }
            float b2 = fmaf(pz, pz, fmaf(py, py, px * px));
#pragma unroll
            for (int j = 0; j < JT; j++) {
                float tq = fmaf(mx[j], px,
                            fmaf(my[j], py,
                             fmaf(mz[j], pz, b2)));
                acc[j] = fminf(acc[j], tq);
            }
        }
    }

    // Epilogue: fold |a|^2 (recompute from pred; constant shift commutes with min).
#pragma unroll
    for (int j = 0; j < JT; j++) {
        float ax = jp[j * 3 + 0];
        float ay = jp[j * 3 + 1];
        float az = jp[j * 3 + 2];
        acc[j] += fmaf(az, az, fmaf(ay, ay, ax * ax));
    }

    // Warp min-reduce.
#pragma unroll
    for (int j = 0; j < JT; j++) {
        float v = acc[j];
        v = fminf(v, __shfl_xor_sync(0xFFFFFFFFu, v, 16));
        v = fminf(v, __shfl_xor_sync(0xFFFFFFFFu, v, 8));
        v = fminf(v, __shfl_xor_sync(0xFFFFFFFFu, v, 4));
        v = fminf(v, __shfl_xor_sync(0xFFFFFFFFu, v, 2));
        v = fminf(v, __shfl_xor_sync(0xFFFFFFFFu, v, 1));
        acc[j] = v;
    }

    // Reuse smem tile as reduction scratch (all main-loop LDS reads complete).
    __syncthreads();
    float* sred = (float*)s_buf4;                 // [0..111]: smin[8][14]
    unsigned* sflag = ((unsigned*)s_buf4) + 120;  // flag slot
    float* ssum = ((float*)s_buf4) + 128;         // per-warp sums

    const int w = t >> 5, l = t & 31;
    if (l == 0) {
#pragma unroll
        for (int j = 0; j < JT; j++) sred[w * JT + j] = acc[j];
    }
    __syncthreads();

    if (t < JT) {
        float v = sred[t];
#pragma unroll
        for (int wi = 1; wi < NWARP; wi++) v = fminf(v, sred[wi * JT + t]);
        g_partial[(size_t)(b * JJ + jg * JT + t) * PC + pc] = v;
    }

    // ---- last-block finalize (fused MSE) ----
    __threadfence();
    __syncthreads();
    if (t == 0) {
        unsigned c = atomicAdd(&g_count, 1u);
        *sflag = (c == (unsigned)(GRID - 1)) ? 1u : 0u;
    }
    __syncthreads();
    if (*sflag == 0u) return;

    // Last block: all partials globally visible (L2-hot).
    float s = 0.0f;
    const float4* gp = (const float4*)g_partial;
#pragma unroll 1
    for (int i = t; i < NBJ; i += THREADS) {
        float4 v = __ldcg(gp + i);
        float m = fminf(fminf(v.x, v.y), fminf(v.z, v.w));
        m = fmaxf(m, 0.0f);
        float d = sqrtf(m) - gt[i];
        s = fmaf(d, d, s);
    }
    // Deterministic fixed-order reduction.
    s += __shfl_xor_sync(0xFFFFFFFFu, s, 16);
    s += __shfl_xor_sync(0xFFFFFFFFu, s, 8);
    s += __shfl_xor_sync(0xFFFFFFFFu, s, 4);
    s += __shfl_xor_sync(0xFFFFFFFFu, s, 2);
    s += __shfl_xor_sync(0xFFFFFFFFu, s, 1);
    __syncthreads();
    if (l == 0) ssum[w] = s;
    __syncthreads();
    if (t == 0) {
        float tot = ssum[0];
#pragma unroll
        for (int wi = 1; wi < NWARP; wi++) tot += ssum[wi];
        out[0] = tot / (float)NBJ;
        g_count = 0;   // reset for next graph replay
    }
}

extern "C" void kernel_launch(void* const* d_in, const int* in_sizes, int n_in,
                              void* d_out, int out_size) {
    (void)in_sizes; (void)n_in; (void)out_size;
    const float* pred = (const float*)d_in[0];   // [64,42,3]
    const float* pts  = (const float*)d_in[1];   // [64,16384,3]
    const float* gt   = (const float*)d_in[2];   // [64,42]
    float* out = (float*)d_out;

    sdl_fused_kernel<<<GRID, THREADS>>>(pred, pts, gt, out);
}

// round 12
// speedup vs baseline: 1.7288x; 1.3028x over previous
#include <cuda_runtime.h>
#include <math.h>

// Problem constants
#define BB 64
#define JJ 42
#define PP 16384
#define JG 3            // joint groups
#define JT 14           // joints per group (JG*JT == JJ)
#define PC 4            // P chunks
#define PPB (PP/PC)     // 4096 points per block
#define THREADS 256
#define PPT (PPB/THREADS)   // 16 points per thread
#define NWARP (THREADS/32)
#define GRID (BB*JG*PC)     // 768 blocks
#define NBJ (BB*JJ)         // 2688

// Scratch: per-(b,j) partial min-squared-distance, one slot per P-chunk.
__device__ float g_partial[NBJ * PC];

// X-macro over the 14 joints: forces fully-scalar named variables (no arrays
// anywhere -> ptxas cannot demote to local memory).
#define FOR_J(X) X(0) X(1) X(2) X(3) X(4) X(5) X(6) X(7) X(8) X(9) X(10) X(11) X(12) X(13)

__global__ void sdl_min_kernel(
    const float* __restrict__ pred,   // [B,J,3]
    const float* __restrict__ pts)    // [B,P,3]
{
    const int blk = blockIdx.x;
    const int pc = blk % PC;
    const int jg = (blk / PC) % JG;
    const int b  = blk / (PC * JG);
    const int t  = threadIdx.x;

    const float* jp = pred + (size_t)(b * JJ + jg * JT) * 3;

    // 70 named scalars: mx/my/mz/acc per joint (a2 folded in epilogue).
#define DECL(n) float mx##n, my##n, mz##n, acc##n;
    FOR_J(DECL)
#undef DECL

#define INIT(n) { float ax = jp[3*n+0], ay = jp[3*n+1], az = jp[3*n+2]; \
                  mx##n = -2.0f*ax; my##n = -2.0f*ay; mz##n = -2.0f*az; \
                  acc##n = 3.0e38f; }
    FOR_J(INIT)
#undef INIT

    // Points for this (b, pc): 4096 points via aligned float4 loads.
    const float4* p4 = (const float4*)(pts + ((size_t)b * PP + (size_t)pc * PPB) * 3);

#pragma unroll 1
    for (int it = 0; it < PPT / 4; it++) {
        const int f4 = it * (THREADS * 3) + t * 3;
        float4 A  = p4[f4 + 0];
        float4 Bv = p4[f4 + 1];
        float4 C  = p4[f4 + 2];

        // 4 points, processed one at a time (per-q scalars only).
#pragma unroll
        for (int q = 0; q < 4; q++) {
            float px, py, pz;
            if (q == 0)      { px = A.x;  py = A.y;  pz = A.z;  }
            else if (q == 1) { px = A.w;  py = Bv.x; pz = Bv.y; }
            else if (q == 2) { px = Bv.z; py = Bv.w; pz = C.x;  }
            else             { px = C.y;  py = C.z;  pz = C.w;  }
            float b2 = fmaf(pz, pz, fmaf(py, py, px * px));
#define UPD(n) { float tq = fmaf(mx##n, px, fmaf(my##n, py, fmaf(mz##n, pz, b2))); \
                 acc##n = fminf(acc##n, tq); }
            FOR_J(UPD)
#undef UPD
        }
    }

    // Epilogue: fold |a|^2, warp min-reduce, write to smem per joint.
    __shared__ float smin[NWARP][JT];
    const int w = t >> 5, l = t & 31;

#define FIN(n) { float ax = jp[3*n+0], ay = jp[3*n+1], az = jp[3*n+2]; \
                 float v = acc##n + fmaf(az, az, fmaf(ay, ay, ax*ax)); \
                 v = fminf(v, __shfl_xor_sync(0xFFFFFFFFu, v, 16)); \
                 v = fminf(v, __shfl_xor_sync(0xFFFFFFFFu, v, 8));  \
                 v = fminf(v, __shfl_xor_sync(0xFFFFFFFFu, v, 4));  \
                 v = fminf(v, __shfl_xor_sync(0xFFFFFFFFu, v, 2));  \
                 v = fminf(v, __shfl_xor_sync(0xFFFFFFFFu, v, 1));  \
                 if (l == 0) smin[w][n] = v; }
    FOR_J(FIN)
#undef FIN

    __syncthreads();

    if (t < JT) {
        float v = smin[0][t];
#pragma unroll
        for (int wi = 1; wi < NWARP; wi++) v = fminf(v, smin[wi][t]);
        g_partial[(size_t)(b * JJ + jg * JT + t) * PC + pc] = v;
    }
}

// Finalize: single block, 1024 threads (deterministic, parallel enough).
__global__ __launch_bounds__(1024) void sdl_mse_kernel(
    const float* __restrict__ gt,   // [B,J]
    float* __restrict__ out)
{
    const int t = threadIdx.x;
    float s = 0.0f;
    const float4* gp = (const float4*)g_partial;
#pragma unroll
    for (int k = 0; k < 3; k++) {
        int i = t + k * 1024;
        if (i < NBJ) {
            float4 v = __ldcg(gp + i);
            float m = fminf(fminf(v.x, v.y), fminf(v.z, v.w));
            m = fmaxf(m, 0.0f);
            float d = sqrtf(m) - gt[i];
            s = fmaf(d, d, s);
        }
    }
    s += __shfl_xor_sync(0xFFFFFFFFu, s, 16);
    s += __shfl_xor_sync(0xFFFFFFFFu, s, 8);
    s += __shfl_xor_sync(0xFFFFFFFFu, s, 4);
    s += __shfl_xor_sync(0xFFFFFFFFu, s, 2);
    s += __shfl_xor_sync(0xFFFFFFFFu, s, 1);
    __shared__ float ssum[32];
    const int w = t >> 5, l = t & 31;
    if (l == 0) ssum[w] = s;
    __syncthreads();
    if (t == 0) {
        float tot = ssum[0];
#pragma unroll
        for (int wi = 1; wi < 32; wi++) tot += ssum[wi];
        out[0] = tot / (float)NBJ;
    }
}

extern "C" void kernel_launch(void* const* d_in, const int* in_sizes, int n_in,
                              void* d_out, int out_size) {
    (void)in_sizes; (void)n_in; (void)out_size;
    const float* pred = (const float*)d_in[0];   // [64,42,3]
    const float* pts  = (const float*)d_in[1];   // [64,16384,3]
    const float* gt   = (const float*)d_in[2];   // [64,42]
    float* out = (float*)d_out;

    sdl_min_kernel<<<GRID, THREADS>>>(pred, pts);
    sdl_mse_kernel<<<1, 1024>>>(gt, out);
}